// round 13
// baseline (speedup 1.0000x reference)
#include <cuda_runtime.h>
#include <math.h>

#define BB 16
#define LL 512
#define DD 128
#define CPB 8          // CTAs per batch
#define RPC 16         // rows per CTA (DD / CPB)

// ---------------- device scratch (no allocations allowed) ----------------
__device__ __align__(128) float g_kphi[BB * LL * DD];
__device__ __align__(128) float g_qphi[BB * LL * DD];
__device__ __align__(128) float g_qraw[BB * LL * DD];
__device__ __align__(128) float g_ys[BB * LL * DD];
__device__ __align__(128) float g_S[2 * BB * DD * DD];   // parity double buffer
__device__ __align__(128) float g_np[2 * BB * CPB];      // frob-norm partials
__device__ __align__(128) unsigned g_bar[2 * BB];        // [0..B): count, [B..2B): generation

// ---------------- kernel 1a: q = xWq^T ; k = normalize(xWk^T) -> kphi ----
__global__ void __launch_bounds__(256) k_qk(const float* __restrict__ x,
                                            const float* __restrict__ Wq,
                                            const float* __restrict__ Wk,
                                            const float* __restrict__ coeffs) {
    extern __shared__ float sm[];
    float* Wqs = sm;                  // 128*129
    float* Wks = Wqs + 128 * 129;     // 128*129
    float* xr  = Wks + 128 * 129;     // 128
    float* kr  = xr + 128;            // 128
    float* rnv = kr + 128;            // 1

    int tid = threadIdx.x;
    int b = blockIdx.x, lc = blockIdx.y;

    for (int idx = tid; idx < DD * DD; idx += 256) {
        int e = idx >> 7, d = idx & 127;
        Wqs[e * 129 + d] = Wq[idx];
        Wks[e * 129 + d] = Wk[idx];
    }
    float c0 = coeffs[0], c1 = coeffs[1];
    __syncthreads();

    for (int li = 0; li < 64; li++) {
        int l = lc * 64 + li;
        size_t base = ((size_t)(b * LL + l)) << 7;
        if (tid < 128) xr[tid] = x[base + tid];
        __syncthreads();
        if (tid < 128) {
            float acc = 0.f;
            const float* wr = Wqs + tid * 129;
#pragma unroll 8
            for (int d = 0; d < 128; d++) acc += xr[d] * wr[d];
            g_qraw[base + tid] = acc;
        } else {
            int e = tid - 128;
            float acc = 0.f;
            const float* wr = Wks + e * 129;
#pragma unroll 8
            for (int d = 0; d < 128; d++) acc += xr[d] * wr[d];
            kr[e] = acc;
        }
        __syncthreads();
        if (tid < 32) {
            float s = 0.f;
#pragma unroll
            for (int j = tid; j < 128; j += 32) { float v = kr[j]; s += v * v; }
            for (int o = 16; o; o >>= 1) s += __shfl_xor_sync(0xffffffffu, s, o);
            if (tid == 0) rnv[0] = 1.0f / fmaxf(sqrtf(s), 1e-12f);
        }
        __syncthreads();
        if (tid < 128) {
            float kn = kr[tid] * rnv[0];
            g_kphi[base + tid] = c0 * kn + c1 * kn * kn;
        }
        __syncthreads();
    }
}

// ---------------- kernel 1b: q_aligned = tanh(gain * q@P0) -> qphi -------
__global__ void __launch_bounds__(128) k_qalign(const float* __restrict__ P0,
                                                const float* __restrict__ log_gain,
                                                const float* __restrict__ coeffs) {
    extern __shared__ float sm[];
    float* Ps = sm;            // 128*128 (unpadded: column access is conflict-free)
    float* qr = Ps + 128 * 128;

    int tid = threadIdx.x;
    int b = blockIdx.x, lc = blockIdx.y;

    for (int idx = tid; idx < DD * DD; idx += 128) Ps[idx] = P0[idx];
    float gain = expf(log_gain[tid]);
    float c0 = coeffs[0], c1 = coeffs[1];
    __syncthreads();

    for (int li = 0; li < 64; li++) {
        int l = lc * 64 + li;
        size_t base = ((size_t)(b * LL + l)) << 7;
        qr[tid] = g_qraw[base + tid];
        __syncthreads();
        float acc = 0.f;
#pragma unroll 8
        for (int d = 0; d < 128; d++) acc += qr[d] * Ps[d * 128 + tid];
        float qa = tanhf(gain * acc);
        g_qphi[base + tid] = c0 * qa + c1 * qa * qa;
        __syncthreads();
    }
}

// ---------------- kernel 2: the sequential scan (persistent, 128 CTAs) ---
__global__ void __launch_bounds__(256) k_scan(const float* __restrict__ x,
                                              const float* __restrict__ M0,
                                              const float* __restrict__ S0) {
    extern __shared__ float sm[];
    float* Sf   = sm;                 // 128*129  full S (padded)
    float* Ms   = Sf + 128 * 129;     // 16*128   local M rows
    float* Ts   = Ms + 16 * 128;      // 16*129   T = S_R * S^T (padded)
    float* kv   = Ts + 16 * 129;      // 128
    float* qv   = kv + 128;           // 128
    float* xv   = qv + 128;           // 128
    float* errs = xv + 128;           // 16
    float* red  = errs + 16;          // 8
    float* sc   = red + 8;            // 2 (coef for S, coef for U)

    int tid = threadIdx.x;
    int bx = blockIdx.x;
    int b = bx >> 3, c = bx & 7;
    int r0 = c * RPC;
    int lane = tid & 31, w = tid >> 5;

    // init state: S full, M rows
    for (int idx = tid; idx < DD * DD; idx += 256) {
        int r = idx >> 7, col = idx & 127;
        Sf[r * 129 + col] = S0[idx];
    }
    for (int idx = tid; idx < RPC * DD; idx += 256)
        Ms[idx] = M0[r0 * DD + idx];
    __syncthreads();

    const float* kbase = g_kphi + (((size_t)b * LL) << 7);
    const float* qbase = g_qphi + (((size_t)b * LL) << 7);
    const float* xbase = x + (((size_t)b * LL) << 7);
    float* Sg0 = g_S + (size_t)b * DD * DD;
    float* Sg1 = g_S + (size_t)(BB + b) * DD * DD;

    // matmul tiling: warp -> (it, nt); i in [4it,4it+4), n in {64nt+lane, 64nt+lane+32}
    int it = w >> 1, nt = w & 1;
    int ib = it * 4;
    int n0 = nt * 64 + lane;

    for (int t = 0; t < LL; t++) {
        int p = t & 1;
        float* Sg = p ? Sg1 : Sg0;

        // ---- load step vectors ----
        if (tid < 128) {
            kv[tid] = kbase[(t << 7) + tid];
            qv[tid] = qbase[(t << 7) + tid];
            xv[tid] = xbase[(t << 7) + tid];
        }
        __syncthreads();

        // ---- pred = M_old k ; err = pred - x_t (rows r0..r0+15) ----
        {
            int i0 = w * 2;
            float a0 = 0.f, a1 = 0.f;
            const float* m0r = Ms + i0 * DD;
            const float* m1r = m0r + DD;
#pragma unroll
            for (int j = lane; j < DD; j += 32) {
                float kk = kv[j];
                a0 += m0r[j] * kk;
                a1 += m1r[j] * kk;
            }
            for (int o = 16; o; o >>= 1) {
                a0 += __shfl_xor_sync(0xffffffffu, a0, o);
                a1 += __shfl_xor_sync(0xffffffffu, a1, o);
            }
            if (lane == 0) {
                errs[i0]     = a0 - xv[r0 + i0];
                errs[i0 + 1] = a1 - xv[r0 + i0 + 1];
            }
        }
        __syncthreads();

        // ---- new S rows: 0.9*S + err (x) k ; write to global, partial frob ----
        float ssq = 0.f;
        {
            int row = tid >> 4;
            int col0 = (tid & 15) << 3;
            float e = errs[row];
            const float* sfr = Sf + (r0 + row) * 129 + col0;
            float o4[8];
#pragma unroll
            for (int ci = 0; ci < 8; ci++) {
                float v = 0.9f * sfr[ci] + e * kv[col0 + ci];
                o4[ci] = v;
                ssq += v * v;
            }
            float4* dst = reinterpret_cast<float4*>(Sg + (size_t)(r0 + row) * DD + col0);
            __stcg(dst,     make_float4(o4[0], o4[1], o4[2], o4[3]));
            __stcg(dst + 1, make_float4(o4[4], o4[5], o4[6], o4[7]));
        }
        for (int o = 16; o; o >>= 1) ssq += __shfl_xor_sync(0xffffffffu, ssq, o);
        if (lane == 0) red[w] = ssq;
        __syncthreads();

        // ---- per-batch barrier (8 CTAs), exchange norm partials ----
        if (tid == 0) {
            float part = 0.f;
#pragma unroll
            for (int j = 0; j < 8; j++) part += red[j];
            __stcg(&g_np[(p * BB + b) * CPB + c], part);
            __threadfence();
            unsigned target = (unsigned)(t + 1);
            if (atomicAdd(&g_bar[b], 1u) == CPB - 1) {
                atomicExch(&g_bar[b], 0u);
                __threadfence();
                atomicAdd(&g_bar[BB + b], 1u);   // gen -> target
            } else {
                while (atomicAdd(&g_bar[BB + b], 0u) < target) { }
            }
            __threadfence();
            float tot = 0.f;
#pragma unroll
            for (int j = 0; j < CPB; j++) tot += __ldcg(&g_np[(p * BB + b) * CPB + j]);
            float inv = 1.0f / (sqrtf(tot) + 1e-6f);
            sc[0] = 0.015f * inv;               // coef for -S term
            sc[1] = 0.005f * inv * inv * inv;   // coef for +U term
        }
        __syncthreads();

        // ---- reload full new S (L2 bypassing L1) ----
        {
            int row = tid >> 1;
            int cb = (tid & 1) << 6;
            const float4* src = reinterpret_cast<const float4*>(Sg + (size_t)row * DD + cb);
            float* drow = Sf + row * 129 + cb;
#pragma unroll
            for (int j = 0; j < 16; j++) {
                float4 v = __ldcg(src + j);
                drow[4 * j + 0] = v.x; drow[4 * j + 1] = v.y;
                drow[4 * j + 2] = v.z; drow[4 * j + 3] = v.w;
            }
        }
        __syncthreads();

        // ---- T = S_R * S^T  (T[i][n] = sum_k S[r0+i][k] * S[n][k]) ----
        {
            float acc00=0,acc01=0,acc10=0,acc11=0,acc20=0,acc21=0,acc30=0,acc31=0;
            const float* a0r = Sf + (r0 + ib) * 129;
            const float* a1r = a0r + 129;
            const float* a2r = a1r + 129;
            const float* a3r = a2r + 129;
            const float* b0r = Sf + n0 * 129;
            const float* b1r = Sf + (n0 + 32) * 129;
#pragma unroll 4
            for (int k = 0; k < 128; k++) {
                float bb0 = b0r[k], bb1 = b1r[k];
                float a0 = a0r[k], a1 = a1r[k], a2 = a2r[k], a3 = a3r[k];
                acc00 += a0 * bb0; acc01 += a0 * bb1;
                acc10 += a1 * bb0; acc11 += a1 * bb1;
                acc20 += a2 * bb0; acc21 += a2 * bb1;
                acc30 += a3 * bb0; acc31 += a3 * bb1;
            }
            Ts[(ib + 0) * 129 + n0] = acc00; Ts[(ib + 0) * 129 + n0 + 32] = acc01;
            Ts[(ib + 1) * 129 + n0] = acc10; Ts[(ib + 1) * 129 + n0 + 32] = acc11;
            Ts[(ib + 2) * 129 + n0] = acc20; Ts[(ib + 2) * 129 + n0 + 32] = acc21;
            Ts[(ib + 3) * 129 + n0] = acc30; Ts[(ib + 3) * 129 + n0 + 32] = acc31;
        }
        __syncthreads();

        // ---- U = T * S, fused M update: M = 0.99M - sc0*S + sc1*U ----
        {
            float acc00=0,acc01=0,acc10=0,acc11=0,acc20=0,acc21=0,acc30=0,acc31=0;
            const float* t0r = Ts + ib * 129;
            const float* t1r = t0r + 129;
            const float* t2r = t1r + 129;
            const float* t3r = t2r + 129;
#pragma unroll 4
            for (int k = 0; k < 128; k++) {
                const float* srw = Sf + k * 129;
                float bb0 = srw[n0], bb1 = srw[n0 + 32];
                float a0 = t0r[k], a1 = t1r[k], a2 = t2r[k], a3 = t3r[k];
                acc00 += a0 * bb0; acc01 += a0 * bb1;
                acc10 += a1 * bb0; acc11 += a1 * bb1;
                acc20 += a2 * bb0; acc21 += a2 * bb1;
                acc30 += a3 * bb0; acc31 += a3 * bb1;
            }
            float sco = sc[0], uco = sc[1];
            float u0[4] = {acc00, acc10, acc20, acc30};
            float u1[4] = {acc01, acc11, acc21, acc31};
#pragma unroll
            for (int ii = 0; ii < 4; ii++) {
                int i = ib + ii;
                float* mr = Ms + i * DD;
                const float* sr = Sf + (r0 + i) * 129;
                mr[n0]      = 0.99f * mr[n0]      - sco * sr[n0]      + uco * u0[ii];
                mr[n0 + 32] = 0.99f * mr[n0 + 32] - sco * sr[n0 + 32] + uco * u1[ii];
            }
        }
        __syncthreads();

        // ---- y_t = M_new q ----
        {
            int i0 = w * 2;
            float a0 = 0.f, a1 = 0.f;
            const float* m0r = Ms + i0 * DD;
            const float* m1r = m0r + DD;
#pragma unroll
            for (int j = lane; j < DD; j += 32) {
                float qq = qv[j];
                a0 += m0r[j] * qq;
                a1 += m1r[j] * qq;
            }
            for (int o = 16; o; o >>= 1) {
                a0 += __shfl_xor_sync(0xffffffffu, a0, o);
                a1 += __shfl_xor_sync(0xffffffffu, a1, o);
            }
            if (lane == 0) {
                size_t yb = (((size_t)(b * LL + t)) << 7) + r0;
                g_ys[yb + i0] = a0;
                g_ys[yb + i0 + 1] = a1;
            }
        }
        __syncthreads();
    }
}

// ---------------- kernel 3: out = ys @ Wout^T + bout ---------------------
__global__ void __launch_bounds__(128) k_out(const float* __restrict__ Wout,
                                             const float* __restrict__ bout,
                                             float* __restrict__ out) {
    extern __shared__ float sm[];
    float* Ws = sm;              // 128*129
    float* yr = Ws + 128 * 129;  // 128

    int tid = threadIdx.x;
    int b = blockIdx.x, lc = blockIdx.y;

    for (int idx = tid; idx < DD * DD; idx += 128) {
        int e = idx >> 7, d = idx & 127;
        Ws[e * 129 + d] = Wout[idx];
    }
    float be = bout[tid];
    __syncthreads();

    for (int li = 0; li < 64; li++) {
        int l = lc * 64 + li;
        size_t base = ((size_t)(b * LL + l)) << 7;
        yr[tid] = g_ys[base + tid];
        __syncthreads();
        float acc = 0.f;
        const float* wr = Ws + tid * 129;
#pragma unroll 8
        for (int d = 0; d < 128; d++) acc += yr[d] * wr[d];
        out[base + tid] = acc + be;
        __syncthreads();
    }
}

// ---------------- launch -------------------------------------------------
extern "C" void kernel_launch(void* const* d_in, const int* in_sizes, int n_in,
                              void* d_out, int out_size) {
    (void)in_sizes; (void)n_in; (void)out_size;
    const float* x    = (const float*)d_in[0];
    const float* Wq   = (const float*)d_in[1];
    const float* Wk   = (const float*)d_in[2];
    const float* P0   = (const float*)d_in[3];
    const float* M0   = (const float*)d_in[4];
    const float* S0   = (const float*)d_in[5];
    const float* lg   = (const float*)d_in[6];
    const float* co   = (const float*)d_in[7];
    const float* Wout = (const float*)d_in[8];
    const float* bout = (const float*)d_in[9];
    float* out = (float*)d_out;

    // reset barrier state every launch (idempotent, capture-safe)
    void* barptr = nullptr;
    cudaGetSymbolAddress(&barptr, g_bar);
    cudaMemsetAsync(barptr, 0, sizeof(unsigned) * 2 * BB, 0);

    size_t sm1  = (size_t)(2 * 128 * 129 + 128 + 128 + 8) * sizeof(float);
    size_t sm1b = (size_t)(128 * 128 + 128) * sizeof(float);
    size_t sm2  = (size_t)(128 * 129 + 16 * 128 + 16 * 129 + 3 * 128 + 16 + 8 + 8) * sizeof(float);
    size_t sm3  = (size_t)(128 * 129 + 128) * sizeof(float);
    cudaFuncSetAttribute(k_qk,     cudaFuncAttributeMaxDynamicSharedMemorySize, (int)sm1);
    cudaFuncSetAttribute(k_qalign, cudaFuncAttributeMaxDynamicSharedMemorySize, (int)sm1b);
    cudaFuncSetAttribute(k_scan,   cudaFuncAttributeMaxDynamicSharedMemorySize, (int)sm2);
    cudaFuncSetAttribute(k_out,    cudaFuncAttributeMaxDynamicSharedMemorySize, (int)sm3);

    dim3 gA(BB, 8);
    k_qk<<<gA, 256, sm1>>>(x, Wq, Wk, co);
    k_qalign<<<gA, 128, sm1b>>>(P0, lg, co);
    k_scan<<<BB * CPB, 256, sm2>>>(x, M0, S0);
    k_out<<<gA, 128, sm3>>>(Wout, bout, out);
}

// round 17
// speedup vs baseline: 1.1988x; 1.1988x over previous
#include <cuda_runtime.h>
#include <math.h>

#define BB 16
#define LL 512
#define DD 128
#define CPB 8          // CTAs per batch
#define RPC 16         // rows per CTA (DD / CPB)
#define SFS 132        // padded smem row stride (≡4 mod 32: float4 row-gather conflict-free)

// ---------------- device scratch (no allocations allowed) ----------------
__device__ __align__(128) float g_kphi[BB * LL * DD];
__device__ __align__(128) float g_qphi[BB * LL * DD];
__device__ __align__(128) float g_qraw[BB * LL * DD];
__device__ __align__(128) float g_ys[BB * LL * DD];
__device__ __align__(128) float g_S[2 * BB * DD * DD];   // parity double buffer
__device__ __align__(128) float g_np[2 * BB * CPB];      // frob-norm partials
__device__ __align__(128) unsigned g_bar[2 * BB];        // [0..B): count, [B..2B): generation

// ---------------- kernel 1a: q = xWq^T ; k = normalize(xWk^T) -> kphi ----
__global__ void __launch_bounds__(256) k_qk(const float* __restrict__ x,
                                            const float* __restrict__ Wq,
                                            const float* __restrict__ Wk,
                                            const float* __restrict__ coeffs) {
    extern __shared__ float sm[];
    float* Wqs = sm;                  // 128*129
    float* Wks = Wqs + 128 * 129;     // 128*129
    float* xr  = Wks + 128 * 129;     // 128
    float* kr  = xr + 128;            // 128
    float* rnv = kr + 128;            // 1

    int tid = threadIdx.x;
    int b = blockIdx.x, lc = blockIdx.y;

    // prefetch first x row before the weight fill so latency overlaps
    float xn = 0.f;
    {
        size_t base0 = ((size_t)(b * LL + lc * 64)) << 7;
        if (tid < 128) xn = x[base0 + tid];
    }
    for (int idx = tid; idx < DD * DD; idx += 256) {
        int e = idx >> 7, d = idx & 127;
        Wqs[e * 129 + d] = Wq[idx];
        Wks[e * 129 + d] = Wk[idx];
    }
    float c0 = coeffs[0], c1 = coeffs[1];
    __syncthreads();

    for (int li = 0; li < 64; li++) {
        int l = lc * 64 + li;
        size_t base = ((size_t)(b * LL + l)) << 7;
        if (tid < 128) xr[tid] = xn;
        __syncthreads();
        if (li + 1 < 64 && tid < 128) xn = x[base + 128 + tid];
        if (tid < 128) {
            float acc = 0.f;
            const float* wr = Wqs + tid * 129;
#pragma unroll 8
            for (int d = 0; d < 128; d++) acc += xr[d] * wr[d];
            g_qraw[base + tid] = acc;
        } else {
            int e = tid - 128;
            float acc = 0.f;
            const float* wr = Wks + e * 129;
#pragma unroll 8
            for (int d = 0; d < 128; d++) acc += xr[d] * wr[d];
            kr[e] = acc;
        }
        __syncthreads();
        if (tid < 32) {
            float s = 0.f;
#pragma unroll
            for (int j = tid; j < 128; j += 32) { float v = kr[j]; s += v * v; }
            for (int o = 16; o; o >>= 1) s += __shfl_xor_sync(0xffffffffu, s, o);
            if (tid == 0) rnv[0] = 1.0f / fmaxf(sqrtf(s), 1e-12f);
        }
        __syncthreads();
        if (tid < 128) {
            float kn = kr[tid] * rnv[0];
            g_kphi[base + tid] = c0 * kn + c1 * kn * kn;
        }
        __syncthreads();
    }
}

// ---------------- kernel 1b: q_aligned = tanh(gain * q@P0) -> qphi -------
__global__ void __launch_bounds__(128) k_qalign(const float* __restrict__ P0,
                                                const float* __restrict__ log_gain,
                                                const float* __restrict__ coeffs) {
    extern __shared__ float sm[];
    float* Ps = sm;            // 128*128 (unpadded: column access is conflict-free)
    float* qr = Ps + 128 * 128;

    int tid = threadIdx.x;
    int b = blockIdx.x, lc = blockIdx.y;
    const int NL = 16;

    float qn;
    {
        size_t base0 = ((size_t)(b * LL + lc * NL)) << 7;
        qn = g_qraw[base0 + tid];
    }
    for (int idx = tid; idx < DD * DD; idx += 128) Ps[idx] = P0[idx];
    float gain = expf(log_gain[tid]);
    float c0 = coeffs[0], c1 = coeffs[1];
    __syncthreads();

    for (int li = 0; li < NL; li++) {
        int l = lc * NL + li;
        size_t base = ((size_t)(b * LL + l)) << 7;
        qr[tid] = qn;
        __syncthreads();
        if (li + 1 < NL) qn = g_qraw[base + 128 + tid];
        float acc = 0.f;
#pragma unroll 8
        for (int d = 0; d < 128; d++) acc += qr[d] * Ps[d * 128 + tid];
        float qa = tanhf(gain * acc);
        g_qphi[base + tid] = c0 * qa + c1 * qa * qa;
        __syncthreads();
    }
}

// ---------------- kernel 2: the sequential scan (persistent, 128 CTAs) ---
__global__ void __launch_bounds__(256, 1) k_scan(const float* __restrict__ x,
                                                 const float* __restrict__ M0,
                                                 const float* __restrict__ S0) {
    extern __shared__ float sm[];
    float* Sf   = sm;                  // 128*SFS  full S (padded, own rows kept current)
    float* Ts   = Sf + 128 * SFS;      // 16*SFS   T = S_R * S^T
    float* Ms   = Ts + 16 * SFS;       // 16*128   local M rows
    float* kv   = Ms + 16 * 128;       // 128
    float* qv   = kv + 128;            // 128
    float* xv   = qv + 128;            // 128
    float* errs = xv + 128;            // 16
    float* red  = errs + 16;           // 8
    float* sc   = red + 8;             // 2

    int tid = threadIdx.x;
    int bx = blockIdx.x;
    int b = bx >> 3, c = bx & 7;
    int r0 = c * RPC;
    int lane = tid & 31, w = tid >> 5;

    const float* kbase = g_kphi + (((size_t)b * LL) << 7);
    const float* qbase = g_qphi + (((size_t)b * LL) << 7);
    const float* xbase = x + (((size_t)b * LL) << 7);
    float* Sg0 = g_S + (size_t)b * DD * DD;
    float* Sg1 = g_S + (size_t)(BB + b) * DD * DD;

    // prefetch step-0 vectors before state init (latency overlap)
    float rk = 0.f, rq = 0.f, rx = 0.f;
    if (tid < 128) { rk = kbase[tid]; rq = qbase[tid]; rx = xbase[tid]; }

    // init state: S full, M rows
    for (int idx = tid; idx < DD * DD; idx += 256) {
        int r = idx >> 7, col = idx & 127;
        Sf[r * SFS + col] = S0[idx];
    }
    for (int idx = tid; idx < RPC * DD; idx += 256)
        Ms[idx] = M0[r0 * DD + idx];
    __syncthreads();

    // matmul tiling: warp -> (it, nt); i in [4it,4it+4), n in {64nt+lane, 64nt+lane+32}
    int it = w >> 1, nt = w & 1;
    int ib = it * 4;
    int n0 = nt * 64 + lane;

    volatile unsigned* genp = (volatile unsigned*)&g_bar[BB + b];

    for (int t = 0; t < LL; t++) {
        int p = t & 1;
        float* Sg = p ? Sg1 : Sg0;

        // ---- publish step vectors, then prefetch next step's ----
        if (tid < 128) { kv[tid] = rk; qv[tid] = rq; xv[tid] = rx; }
        __syncthreads();
        if (t + 1 < LL && tid < 128) {
            size_t o = ((size_t)(t + 1)) << 7;
            rk = kbase[o + tid]; rq = qbase[o + tid]; rx = xbase[o + tid];
        }

        // ---- pred = M_old k ; err = pred - x_t (rows r0..r0+15) ----
        {
            int i0 = w * 2;
            float a0 = 0.f, a1 = 0.f;
            const float* m0r = Ms + i0 * DD;
            const float* m1r = m0r + DD;
#pragma unroll
            for (int j = lane; j < DD; j += 32) {
                float kk = kv[j];
                a0 += m0r[j] * kk;
                a1 += m1r[j] * kk;
            }
            for (int o = 16; o; o >>= 1) {
                a0 += __shfl_xor_sync(0xffffffffu, a0, o);
                a1 += __shfl_xor_sync(0xffffffffu, a1, o);
            }
            if (lane == 0) {
                errs[i0]     = a0 - xv[r0 + i0];
                errs[i0 + 1] = a1 - xv[r0 + i0 + 1];
            }
        }
        __syncthreads();

        // ---- new S rows: 0.9*S + err (x) k ; in-place smem + global, frob partial ----
        float ssq = 0.f;
        {
            int row = tid >> 4;
            int col0 = (tid & 15) << 3;
            float e = errs[row];
            float* sfr = Sf + (r0 + row) * SFS + col0;
            float4 s0 = *(const float4*)(sfr);
            float4 s1 = *(const float4*)(sfr + 4);
            float4 k0 = *(const float4*)(kv + col0);
            float4 k1 = *(const float4*)(kv + col0 + 4);
            float4 o0, o1;
            o0.x = 0.9f * s0.x + e * k0.x;  o0.y = 0.9f * s0.y + e * k0.y;
            o0.z = 0.9f * s0.z + e * k0.z;  o0.w = 0.9f * s0.w + e * k0.w;
            o1.x = 0.9f * s1.x + e * k1.x;  o1.y = 0.9f * s1.y + e * k1.y;
            o1.z = 0.9f * s1.z + e * k1.z;  o1.w = 0.9f * s1.w + e * k1.w;
            ssq = o0.x*o0.x + o0.y*o0.y + o0.z*o0.z + o0.w*o0.w
                + o1.x*o1.x + o1.y*o1.y + o1.z*o1.z + o1.w*o1.w;
            *(float4*)(sfr)     = o0;
            *(float4*)(sfr + 4) = o1;
            float4* dst = (float4*)(Sg + (size_t)(r0 + row) * DD + col0);
            __stcg(dst, o0);
            __stcg(dst + 1, o1);
        }
        for (int o = 16; o; o >>= 1) ssq += __shfl_xor_sync(0xffffffffu, ssq, o);
        if (lane == 0) red[w] = ssq;
        __syncthreads();

        // ---- per-batch barrier (8 CTAs), publish norm partial ----
        if (tid == 0) {
            float part = 0.f;
#pragma unroll
            for (int j = 0; j < 8; j++) part += red[j];
            __stcg(&g_np[(p * BB + b) * CPB + c], part);
            __threadfence();
            unsigned target = (unsigned)(t + 1);
            if (atomicAdd(&g_bar[b], 1u) == CPB - 1) {
                atomicExch(&g_bar[b], 0u);
                __threadfence();
                atomicAdd(&g_bar[BB + b], 1u);   // gen -> target
            } else {
                while (*genp < target) { }
            }
            __threadfence();
        }
        __syncthreads();

        // ---- reload the other 112 rows (L1-bypassing), tid0 gathers norm in parallel ----
        if (tid >= 1 && tid < 225) {
            int idx = tid - 1;
            int row = idx >> 1;
            if (row >= r0) row += RPC;
            int cb = (idx & 1) << 6;
            const float4* src = (const float4*)(Sg + (size_t)row * DD + cb);
            float* drow = Sf + row * SFS + cb;
#pragma unroll
            for (int j = 0; j < 16; j++) {
                float4 v = __ldcg(src + j);
                *(float4*)(drow + 4 * j) = v;
            }
        }
        if (tid == 0) {
            float tot = 0.f;
#pragma unroll
            for (int j = 0; j < CPB; j++) tot += __ldcg(&g_np[(p * BB + b) * CPB + j]);
            float inv = 1.0f / (sqrtf(tot) + 1e-6f);
            sc[0] = 0.015f * inv;               // coef for -S term
            sc[1] = 0.005f * inv * inv * inv;   // coef for +U term
        }
        __syncthreads();

        // ---- T = S_R * S^T, float4 along k both sides ----
        {
            float acc00=0,acc01=0,acc10=0,acc11=0,acc20=0,acc21=0,acc30=0,acc31=0;
            const float4* a0 = (const float4*)(Sf + (r0 + ib) * SFS);
            const float4* a1 = (const float4*)(Sf + (r0 + ib + 1) * SFS);
            const float4* a2 = (const float4*)(Sf + (r0 + ib + 2) * SFS);
            const float4* a3 = (const float4*)(Sf + (r0 + ib + 3) * SFS);
            const float4* b0 = (const float4*)(Sf + n0 * SFS);
            const float4* b1 = (const float4*)(Sf + (n0 + 32) * SFS);
#pragma unroll 4
            for (int k4 = 0; k4 < 32; k4++) {
                float4 B0 = b0[k4], B1 = b1[k4];
                float4 A0 = a0[k4], A1 = a1[k4], A2 = a2[k4], A3 = a3[k4];
                acc00 += A0.x*B0.x + A0.y*B0.y + A0.z*B0.z + A0.w*B0.w;
                acc01 += A0.x*B1.x + A0.y*B1.y + A0.z*B1.z + A0.w*B1.w;
                acc10 += A1.x*B0.x + A1.y*B0.y + A1.z*B0.z + A1.w*B0.w;
                acc11 += A1.x*B1.x + A1.y*B1.y + A1.z*B1.z + A1.w*B1.w;
                acc20 += A2.x*B0.x + A2.y*B0.y + A2.z*B0.z + A2.w*B0.w;
                acc21 += A2.x*B1.x + A2.y*B1.y + A2.z*B1.z + A2.w*B1.w;
                acc30 += A3.x*B0.x + A3.y*B0.y + A3.z*B0.z + A3.w*B0.w;
                acc31 += A3.x*B1.x + A3.y*B1.y + A3.z*B1.z + A3.w*B1.w;
            }
            Ts[(ib + 0) * SFS + n0] = acc00; Ts[(ib + 0) * SFS + n0 + 32] = acc01;
            Ts[(ib + 1) * SFS + n0] = acc10; Ts[(ib + 1) * SFS + n0 + 32] = acc11;
            Ts[(ib + 2) * SFS + n0] = acc20; Ts[(ib + 2) * SFS + n0 + 32] = acc21;
            Ts[(ib + 3) * SFS + n0] = acc30; Ts[(ib + 3) * SFS + n0 + 32] = acc31;
        }
        __syncthreads();

        // ---- U = T * S, fused M update: M = 0.99M - sc0*S + sc1*U ----
        {
            float u00=0,u01=0,u10=0,u11=0,u20=0,u21=0,u30=0,u31=0;
            const float4* t0 = (const float4*)(Ts + (ib + 0) * SFS);
            const float4* t1 = (const float4*)(Ts + (ib + 1) * SFS);
            const float4* t2 = (const float4*)(Ts + (ib + 2) * SFS);
            const float4* t3 = (const float4*)(Ts + (ib + 3) * SFS);
#pragma unroll 2
            for (int k4 = 0; k4 < 32; k4++) {
                float4 T0 = t0[k4], T1 = t1[k4], T2 = t2[k4], T3 = t3[k4];
                const float* s0 = Sf + (4 * k4) * SFS;
                const float* s1 = s0 + SFS;
                const float* s2 = s1 + SFS;
                const float* s3 = s2 + SFS;
                float b00 = s0[n0], b01 = s0[n0 + 32];
                float b10 = s1[n0], b11 = s1[n0 + 32];
                float b20 = s2[n0], b21 = s2[n0 + 32];
                float b30 = s3[n0], b31 = s3[n0 + 32];
                u00 += T0.x*b00 + T0.y*b10 + T0.z*b20 + T0.w*b30;
                u01 += T0.x*b01 + T0.y*b11 + T0.z*b21 + T0.w*b31;
                u10 += T1.x*b00 + T1.y*b10 + T1.z*b20 + T1.w*b30;
                u11 += T1.x*b01 + T1.y*b11 + T1.z*b21 + T1.w*b31;
                u20 += T2.x*b00 + T2.y*b10 + T2.z*b20 + T2.w*b30;
                u21 += T2.x*b01 + T2.y*b11 + T2.z*b21 + T2.w*b31;
                u30 += T3.x*b00 + T3.y*b10 + T3.z*b20 + T3.w*b30;
                u31 += T3.x*b01 + T3.y*b11 + T3.z*b21 + T3.w*b31;
            }
            float sco = sc[0], uco = sc[1];
            float u0[4] = {u00, u10, u20, u30};
            float u1[4] = {u01, u11, u21, u31};
#pragma unroll
            for (int ii = 0; ii < 4; ii++) {
                int i = ib + ii;
                float* mr = Ms + i * DD;
                const float* sr = Sf + (r0 + i) * SFS;
                mr[n0]      = 0.99f * mr[n0]      - sco * sr[n0]      + uco * u0[ii];
                mr[n0 + 32] = 0.99f * mr[n0 + 32] - sco * sr[n0 + 32] + uco * u1[ii];
            }
        }
        __syncthreads();

        // ---- y_t = M_new q ----
        {
            int i0 = w * 2;
            float a0 = 0.f, a1 = 0.f;
            const float* m0r = Ms + i0 * DD;
            const float* m1r = m0r + DD;
#pragma unroll
            for (int j = lane; j < DD; j += 32) {
                float qq = qv[j];
                a0 += m0r[j] * qq;
                a1 += m1r[j] * qq;
            }
            for (int o = 16; o; o >>= 1) {
                a0 += __shfl_xor_sync(0xffffffffu, a0, o);
                a1 += __shfl_xor_sync(0xffffffffu, a1, o);
            }
            if (lane == 0) {
                size_t yb = (((size_t)(b * LL + t)) << 7) + r0;
                g_ys[yb + i0] = a0;
                g_ys[yb + i0 + 1] = a1;
            }
        }
        __syncthreads();
    }
}

// ---------------- kernel 3: out = ys @ Wout^T + bout ---------------------
__global__ void __launch_bounds__(128) k_out(const float* __restrict__ Wout,
                                             const float* __restrict__ bout,
                                             float* __restrict__ out) {
    extern __shared__ float sm[];
    float* Ws = sm;              // 128*129
    float* yr = Ws + 128 * 129;  // 128

    int tid = threadIdx.x;
    int b = blockIdx.x, lc = blockIdx.y;
    const int NL = 16;

    float yn;
    {
        size_t base0 = ((size_t)(b * LL + lc * NL)) << 7;
        yn = g_ys[base0 + tid];
    }
    for (int idx = tid; idx < DD * DD; idx += 128) {
        int e = idx >> 7, d = idx & 127;
        Ws[e * 129 + d] = Wout[idx];
    }
    float be = bout[tid];
    __syncthreads();

    for (int li = 0; li < NL; li++) {
        int l = lc * NL + li;
        size_t base = ((size_t)(b * LL + l)) << 7;
        yr[tid] = yn;
        __syncthreads();
        if (li + 1 < NL) yn = g_ys[base + 128 + tid];
        float acc = 0.f;
        const float* wr = Ws + tid * 129;
#pragma unroll 8
        for (int d = 0; d < 128; d++) acc += yr[d] * wr[d];
        out[base + tid] = acc + be;
        __syncthreads();
    }
}

// ---------------- launch -------------------------------------------------
extern "C" void kernel_launch(void* const* d_in, const int* in_sizes, int n_in,
                              void* d_out, int out_size) {
    (void)in_sizes; (void)n_in; (void)out_size;
    const float* x    = (const float*)d_in[0];
    const float* Wq   = (const float*)d_in[1];
    const float* Wk   = (const float*)d_in[2];
    const float* P0   = (const float*)d_in[3];
    const float* M0   = (const float*)d_in[4];
    const float* S0   = (const float*)d_in[5];
    const float* lg   = (const float*)d_in[6];
    const float* co   = (const float*)d_in[7];
    const float* Wout = (const float*)d_in[8];
    const float* bout = (const float*)d_in[9];
    float* out = (float*)d_out;

    // reset barrier state every launch (idempotent, capture-safe)
    void* barptr = nullptr;
    cudaGetSymbolAddress(&barptr, g_bar);
    cudaMemsetAsync(barptr, 0, sizeof(unsigned) * 2 * BB, 0);

    size_t sm1  = (size_t)(2 * 128 * 129 + 128 + 128 + 8) * sizeof(float);
    size_t sm1b = (size_t)(128 * 128 + 128) * sizeof(float);
    size_t sm2  = (size_t)(128 * SFS + 16 * SFS + 16 * 128 + 3 * 128 + 16 + 8 + 8) * sizeof(float);
    size_t sm3  = (size_t)(128 * 129 + 128) * sizeof(float);
    cudaFuncSetAttribute(k_qk,     cudaFuncAttributeMaxDynamicSharedMemorySize, (int)sm1);
    cudaFuncSetAttribute(k_qalign, cudaFuncAttributeMaxDynamicSharedMemorySize, (int)sm1b);
    cudaFuncSetAttribute(k_scan,   cudaFuncAttributeMaxDynamicSharedMemorySize, (int)sm2);
    cudaFuncSetAttribute(k_out,    cudaFuncAttributeMaxDynamicSharedMemorySize, (int)sm3);

    dim3 gQK(BB, 8);
    dim3 gW(BB, 32);
    k_qk<<<gQK, 256, sm1>>>(x, Wq, Wk, co);
    k_qalign<<<gW, 128, sm1b>>>(P0, lg, co);
    k_scan<<<BB * CPB, 256, sm2>>>(x, M0, S0);
    k_out<<<gW, 128, sm3>>>(Wout, bout, out);
}